// round 3
// baseline (speedup 1.0000x reference)
#include <cuda_runtime.h>
#include <cuda_bf16.h>
#include <cstdint>

#define Bn 8
#define SQn 2048
#define SKn 2048
#define Dh 512
#define QT 128
#define NKT 16
#define NDC 4
#define NQT 16
#define THREADS 256
#define PITCH 136                 // bf16 elements per smem tile row (pad vs 128)
#define TBYTES (128 * PITCH * 2)  // 34816 bytes per tile

__device__ uint32_t g_Qp[Bn * SQn * Dh];
__device__ uint32_t g_Kp[Bn * SKn * Dh];
__device__ uint32_t g_Vp[Bn * SKn * Dh];           // transposed: [b][d][sk]
__device__ float    g_S[(size_t)Bn * SQn * SKn];   // fp32 S strip / packed P

// ---------------- helpers ----------------
__device__ __forceinline__ uint32_t smem_to_u32(const void* p) {
    uint32_t a;
    asm("{ .reg .u64 t; cvta.to.shared.u64 t, %1; cvt.u32.u64 %0, t; }" : "=r"(a) : "l"(p));
    return a;
}
__device__ __forceinline__ uint32_t pack_split(float x) {
    unsigned short h = __bfloat16_as_ushort(__float2bfloat16(x));
    float hf = __bfloat162float(__ushort_as_bfloat16(h));
    unsigned short l = __bfloat16_as_ushort(__float2bfloat16(x - hf));
    return (uint32_t)h | ((uint32_t)l << 16);
}
__device__ __forceinline__ void ldsm4(uint32_t* r, uint32_t addr) {
    asm volatile("ldmatrix.sync.aligned.m8n8.x4.shared.b16 {%0,%1,%2,%3}, [%4];"
        : "=r"(r[0]), "=r"(r[1]), "=r"(r[2]), "=r"(r[3]) : "r"(addr));
}
__device__ __forceinline__ void mma16816(float* c, const uint32_t* a, const uint32_t* b) {
    asm volatile("mma.sync.aligned.m16n8k16.row.col.f32.bf16.bf16.f32 "
        "{%0,%1,%2,%3}, {%4,%5,%6,%7}, {%8,%9}, {%0,%1,%2,%3};"
        : "+f"(c[0]), "+f"(c[1]), "+f"(c[2]), "+f"(c[3])
        : "r"(a[0]), "r"(a[1]), "r"(a[2]), "r"(a[3]), "r"(b[0]), "r"(b[1]));
}

__global__ void prep_kernel(const float* __restrict__ q, const float* __restrict__ k,
                            const float* __restrict__ v) {
    const int n = Bn * SQn * Dh;
    const int stride = gridDim.x * blockDim.x;
    for (int i = blockIdx.x * blockDim.x + threadIdx.x; i < n; i += stride) {
        g_Qp[i] = pack_split(q[i]);
        g_Kp[i] = pack_split(k[i]);
    }
    for (int i = blockIdx.x * blockDim.x + threadIdx.x; i < n; i += stride) {
        int b = i / (SKn * Dh);
        int rem = i - b * (SKn * Dh);
        int sk = rem >> 9, d = rem & 511;
        g_Vp[(((size_t)(b * Dh + d)) << 11) + sk] = pack_split(v[i]);
    }
}

// smem: [0..512) rowmax, [512..1024) rowsum, [1024..) 4 tiles (AH, AL, BH, BL)
#define SMEM_BYTES (1024 + 4 * TBYTES)

__global__ void __launch_bounds__(THREADS, 1)
attn_main(float* __restrict__ out) {
    extern __shared__ char smem[];
    float* rowmax = (float*)smem;
    float* rowsum = (float*)(smem + 512);
    char* AH = smem + 1024;
    char* AL = AH + TBYTES;
    char* BH = AH + 2 * TBYTES;
    char* BL = AH + 3 * TBYTES;
    float* stage = (float*)AH;                 // 128x136 fp32 staging aliases AH+AL

    const uint32_t sA = smem_to_u32(AH);
    const uint32_t sB = smem_to_u32(BH);

    const int tid = threadIdx.x, wid = tid >> 5, lane = tid & 31;
    const int qt = blockIdx.x, b = blockIdx.y;

    const uint32_t* Qb = g_Qp + ((size_t)b * SQn + (size_t)qt * QT) * Dh;
    const uint32_t* Kb = g_Kp + (size_t)b * SKn * Dh;
    const uint32_t* Vt = g_Vp + ((size_t)b * Dh) * SKn;
    float* strip = g_S + ((size_t)(b * NQT + qt)) * ((size_t)QT * SKn);
    const uint32_t* stripU = (const uint32_t*)strip;

    if (tid < 128) { rowmax[tid] = -1e30f; rowsum[tid] = 0.0f; }
    __syncthreads();

    // per-lane ldmatrix address components (byte offsets within a tile)
    // A (x4): rows = base + (lane&7) + ((lane>>3)&1)*8 ; cols k0 + (lane>>4)*8
    const uint32_t aoff = (uint32_t)(((wid * 16 + (lane & 7) + ((lane >> 3) & 1) * 8) * PITCH
                                      + (lane >> 4) * 8) * 2);
    // B (x4): rows(n) = n0 + (lane&7) + (lane>>4)*8 ; cols k0 + ((lane>>3)&1)*8
    const uint32_t boff = (uint32_t)((((lane & 7) + (lane >> 4) * 8) * PITCH
                                      + ((lane >> 3) & 1) * 8) * 2);

    float acc[16][4];

    // ================= PHASE 1: S = Q K^T (bf16x3), spill strip =================
    for (int kt = 0; kt < NKT; kt++) {
        #pragma unroll
        for (int nf = 0; nf < 16; nf++)
            #pragma unroll
            for (int j = 0; j < 4; j++) acc[nf][j] = 0.0f;

        for (int dc = 0; dc < NDC; dc++) {
            for (int p = tid; p < 8192; p += THREADS) {
                int r = p >> 6, c2 = (p & 63) << 1;
                uint32_t off = (uint32_t)((r * PITCH + c2) * 2);
                uint2 wq = *(const uint2*)(Qb + (size_t)r * Dh + dc * 128 + c2);
                *(uint32_t*)(AH + off) = (wq.x & 0xFFFFu) | (wq.y << 16);
                *(uint32_t*)(AL + off) = (wq.x >> 16) | (wq.y & 0xFFFF0000u);
                uint2 wk = *(const uint2*)(Kb + (size_t)(kt * 128 + r) * Dh + dc * 128 + c2);
                *(uint32_t*)(BH + off) = (wk.x & 0xFFFFu) | (wk.y << 16);
                *(uint32_t*)(BL + off) = (wk.x >> 16) | (wk.y & 0xFFFF0000u);
            }
            __syncthreads();
            for (int ks = 0; ks < 8; ks++) {
                uint32_t ah[4], al[4];
                ldsm4(ah, sA + aoff + ks * 32);
                ldsm4(al, sA + aoff + ks * 32 + TBYTES);
                #pragma unroll
                for (int nf2 = 0; nf2 < 8; nf2++) {
                    uint32_t bh[4], bl[4];
                    uint32_t ba = sB + boff + (uint32_t)(nf2 * (16 * PITCH * 2) + ks * 32);
                    ldsm4(bh, ba);
                    ldsm4(bl, ba + TBYTES);
                    mma16816(acc[2 * nf2],     ah, bh);
                    mma16816(acc[2 * nf2],     ah, bh + 0 + 0 + 0 == 0 ? bl : bl); // Ah*Bl
                    mma16816(acc[2 * nf2],     al, bh);
                    mma16816(acc[2 * nf2 + 1], ah, bh + 2);
                    mma16816(acc[2 * nf2 + 1], ah, bl + 2);
                    mma16816(acc[2 * nf2 + 1], al, bh + 2);
                }
            }
            __syncthreads();
        }
        // fragments -> stage + rowmax
        float m0 = -1e30f, m1 = -1e30f;
        int row = wid * 16 + (lane >> 2);
        int colb = (lane & 3) * 2;
        #pragma unroll
        for (int nf = 0; nf < 16; nf++) {
            m0 = fmaxf(m0, fmaxf(acc[nf][0], acc[nf][1]));
            m1 = fmaxf(m1, fmaxf(acc[nf][2], acc[nf][3]));
            *(float2*)&stage[row * PITCH + nf * 8 + colb] = make_float2(acc[nf][0], acc[nf][1]);
            *(float2*)&stage[(row + 8) * PITCH + nf * 8 + colb] = make_float2(acc[nf][2], acc[nf][3]);
        }
        m0 = fmaxf(m0, __shfl_xor_sync(0xffffffffu, m0, 1));
        m0 = fmaxf(m0, __shfl_xor_sync(0xffffffffu, m0, 2));
        m1 = fmaxf(m1, __shfl_xor_sync(0xffffffffu, m1, 1));
        m1 = fmaxf(m1, __shfl_xor_sync(0xffffffffu, m1, 2));
        if ((lane & 3) == 0) {
            rowmax[row] = fmaxf(rowmax[row], m0);
            rowmax[row + 8] = fmaxf(rowmax[row + 8], m1);
        }
        __syncthreads();
        for (int i = tid; i < 4096; i += THREADS) {
            int r = i >> 5, c4 = (i & 31) << 2;
            *(float4*)(strip + (size_t)kt * 16384 + r * 128 + c4) =
                *(const float4*)&stage[r * PITCH + c4];
        }
        __syncthreads();
    }

    // ================= PHASE 2: softmax + pack P in place =================
    for (int i = 0; i < 16; i++) {
        int r = wid * 16 + i;
        float m = rowmax[r];
        float s = 0.0f;
        for (int kt = 0; kt < NKT; kt++) {
            float* addr = strip + (size_t)kt * 16384 + r * 128 + lane * 4;
            float4 vv = *(const float4*)addr;
            float p0 = __expf(vv.x - m), p1 = __expf(vv.y - m);
            float p2 = __expf(vv.z - m), p3 = __expf(vv.w - m);
            s += (p0 + p1) + (p2 + p3);
            uint4 pk;
            pk.x = pack_split(p0); pk.y = pack_split(p1);
            pk.z = pack_split(p2); pk.w = pack_split(p3);
            *(uint4*)addr = pk;
        }
        #pragma unroll
        for (int off = 16; off; off >>= 1) s += __shfl_xor_sync(0xffffffffu, s, off);
        if (lane == 0) rowsum[r] = s;
    }
    __syncthreads();

    // ================= PHASE 3: O = P V (bf16x3) =================
    for (int dc = 0; dc < NDC; dc++) {
        #pragma unroll
        for (int nf = 0; nf < 16; nf++)
            #pragma unroll
            for (int j = 0; j < 4; j++) acc[nf][j] = 0.0f;

        for (int kt = 0; kt < NKT; kt++) {
            for (int p = tid; p < 8192; p += THREADS) {
                int r = p >> 6, c2 = (p & 63) << 1;
                uint32_t off = (uint32_t)((r * PITCH + c2) * 2);
                uint2 w = *(const uint2*)(stripU + (size_t)kt * 16384 + r * 128 + c2);
                *(uint32_t*)(AH + off) = (w.x & 0xFFFFu) | (w.y << 16);
                *(uint32_t*)(AL + off) = (w.x >> 16) | (w.y & 0xFFFF0000u);
                uint2 wv = *(const uint2*)(Vt + (size_t)(dc * 128 + r) * SKn + kt * 128 + c2);
                *(uint32_t*)(BH + off) = (wv.x & 0xFFFFu) | (wv.y << 16);
                *(uint32_t*)(BL + off) = (wv.x >> 16) | (wv.y & 0xFFFF0000u);
            }
            __syncthreads();
            for (int ks = 0; ks < 8; ks++) {
                uint32_t ah[4], al[4];
                ldsm4(ah, sA + aoff + ks * 32);
                ldsm4(al, sA + aoff + ks * 32 + TBYTES);
                #pragma unroll
                for (int nf2 = 0; nf2 < 8; nf2++) {
                    uint32_t bh[4], bl[4];
                    uint32_t ba = sB + boff + (uint32_t)(nf2 * (16 * PITCH * 2) + ks * 32);
                    ldsm4(bh, ba);
                    ldsm4(bl, ba + TBYTES);
                    mma16816(acc[2 * nf2],     ah, bh);
                    mma16816(acc[2 * nf2],     ah, bl);
                    mma16816(acc[2 * nf2],     al, bh);
                    mma16816(acc[2 * nf2 + 1], ah, bh + 2);
                    mma16816(acc[2 * nf2 + 1], ah, bl + 2);
                    mma16816(acc[2 * nf2 + 1], al, bh + 2);
                }
            }
            __syncthreads();
        }
        // epilogue chunk: scale by 1/rowsum and store
        int row = wid * 16 + (lane >> 2);
        float inv0 = 1.0f / rowsum[row];
        float inv1 = 1.0f / rowsum[row + 8];
        float* o0 = out + ((size_t)b * SQn + (size_t)qt * QT + row) * Dh + dc * 128;
        float* o1 = o0 + 8 * Dh;
        int colb = (lane & 3) * 2;
        #pragma unroll
        for (int nf = 0; nf < 16; nf++) {
            *(float2*)(o0 + nf * 8 + colb) = make_float2(acc[nf][0] * inv0, acc[nf][1] * inv0);
            *(float2*)(o1 + nf * 8 + colb) = make_float2(acc[nf][2] * inv1, acc[nf][3] * inv1);
        }
        __syncthreads();
    }
}

extern "C" void kernel_launch(void* const* d_in, const int* in_sizes, int n_in,
                              void* d_out, int out_size) {
    (void)in_sizes; (void)n_in; (void)out_size;
    const float* q = (const float*)d_in[0];
    const float* k = (const float*)d_in[1];
    const float* v = (const float*)d_in[2];
    float* out = (float*)d_out;

    cudaFuncSetAttribute(attn_main, cudaFuncAttributeMaxDynamicSharedMemorySize, SMEM_BYTES);

    prep_kernel<<<1024, 256>>>(q, k, v);
    dim3 grid(NQT, Bn);
    attn_main<<<grid, THREADS, SMEM_BYTES>>>(out);
}

// round 4
// speedup vs baseline: 1.5231x; 1.5231x over previous
#include <cuda_runtime.h>
#include <cuda_bf16.h>
#include <cstdint>

#define Bn 8
#define SQn 2048
#define SKn 2048
#define Dh 512
#define NKT 16
#define NDC 4
#define NQT 16
#define THREADS 512
#define PITCHB 272                 // bytes per smem tile row (136 bf16)
#define TBYTES (128 * PITCHB)      // 34816

__device__ __nv_bfloat16 g_Qh[Bn * SQn * Dh], g_Ql[Bn * SQn * Dh];
__device__ __nv_bfloat16 g_Kh[Bn * SKn * Dh], g_Kl[Bn * SKn * Dh];
__device__ __nv_bfloat16 g_Vh[Bn * SKn * Dh], g_Vl[Bn * SKn * Dh];   // [b][d][sk]
__device__ float g_S[(size_t)Bn * SQn * SKn];
__device__ __nv_bfloat16 g_Ph[(size_t)Bn * SQn * SKn], g_Pl[(size_t)Bn * SQn * SKn];

// ---------------- helpers ----------------
__device__ __forceinline__ uint32_t smem_to_u32(const void* p) {
    uint32_t a;
    asm("{ .reg .u64 t; cvta.to.shared.u64 t, %1; cvt.u32.u64 %0, t; }" : "=r"(a) : "l"(p));
    return a;
}
__device__ __forceinline__ void ldsm4(uint32_t* r, uint32_t addr) {
    asm volatile("ldmatrix.sync.aligned.m8n8.x4.shared.b16 {%0,%1,%2,%3}, [%4];"
        : "=r"(r[0]), "=r"(r[1]), "=r"(r[2]), "=r"(r[3]) : "r"(addr));
}
__device__ __forceinline__ void mma16816(float* c, const uint32_t* a, const uint32_t* b) {
    asm volatile("mma.sync.aligned.m16n8k16.row.col.f32.bf16.bf16.f32 "
        "{%0,%1,%2,%3}, {%4,%5,%6,%7}, {%8,%9}, {%0,%1,%2,%3};"
        : "+f"(c[0]), "+f"(c[1]), "+f"(c[2]), "+f"(c[3])
        : "r"(a[0]), "r"(a[1]), "r"(a[2]), "r"(a[3]), "r"(b[0]), "r"(b[1]));
}
__device__ __forceinline__ void cpasync16(uint32_t dst, const void* src) {
    asm volatile("cp.async.cg.shared.global [%0], [%1], 16;" :: "r"(dst), "l"(src));
}
#define CP_COMMIT() asm volatile("cp.async.commit_group;" ::: "memory")
#define CP_WAIT0()  asm volatile("cp.async.wait_group 0;" ::: "memory")
__device__ __forceinline__ unsigned short us(__nv_bfloat16 h) { return __bfloat16_as_ushort(h); }

// ---------------- prep ----------------
__global__ void prep_qk(const float* __restrict__ q, const float* __restrict__ k) {
    const int n = Bn * SQn * Dh;
    for (int i = blockIdx.x * blockDim.x + threadIdx.x; i < n; i += gridDim.x * blockDim.x) {
        float x = q[i];
        __nv_bfloat16 h = __float2bfloat16(x);
        g_Qh[i] = h;
        g_Ql[i] = __float2bfloat16(x - __bfloat162float(h));
        float y = k[i];
        __nv_bfloat16 g = __float2bfloat16(y);
        g_Kh[i] = g;
        g_Kl[i] = __float2bfloat16(y - __bfloat162float(g));
    }
}
__global__ void prep_v(const float* __restrict__ v) {
    __shared__ float t[32][33];
    const int b = blockIdx.z;
    const int sk0 = blockIdx.x * 32, d0 = blockIdx.y * 32;
    const int tx = threadIdx.x & 31, ty = threadIdx.x >> 5;   // 32 x 8
    #pragma unroll
    for (int rr = 0; rr < 32; rr += 8)
        t[ty + rr][tx] = v[(((size_t)b * SKn + sk0 + ty + rr) << 9) + d0 + tx];
    __syncthreads();
    #pragma unroll
    for (int rr = 0; rr < 32; rr += 8) {
        int d = d0 + ty + rr;
        float x = t[tx][ty + rr];
        __nv_bfloat16 h = __float2bfloat16(x);
        size_t o = ((size_t)b * Dh + d) * SKn + sk0 + tx;
        g_Vh[o] = h;
        g_Vl[o] = __float2bfloat16(x - __bfloat162float(h));
    }
}

#define SMEM_BYTES (1024 + 4 * TBYTES)

__global__ void __launch_bounds__(THREADS, 1)
attn_main(float* __restrict__ out) {
    extern __shared__ char smem[];
    float* rowmax = (float*)smem;
    float* rowsum = (float*)(smem + 512);
    char* AH = smem + 1024;
    float* stage = (float*)AH;                 // 128x136 fp32, aliases AH+AL

    const uint32_t sAH = smem_to_u32(AH);
    const uint32_t sAL = sAH + TBYTES;
    const uint32_t sBH = sAH + 2 * TBYTES;
    const uint32_t sBL = sAH + 3 * TBYTES;

    const int tid = threadIdx.x, wid = tid >> 5, lane = tid & 31;
    const int wq = wid >> 1, nh = wid & 1;
    const int qt = blockIdx.x, b = blockIdx.y;

    const __nv_bfloat16* Qh = g_Qh + ((size_t)b * SQn + qt * 128) * Dh;
    const __nv_bfloat16* Ql = g_Ql + ((size_t)b * SQn + qt * 128) * Dh;
    const __nv_bfloat16* Kh = g_Kh + (size_t)b * SKn * Dh;
    const __nv_bfloat16* Kl = g_Kl + (size_t)b * SKn * Dh;
    const __nv_bfloat16* Vh = g_Vh + (size_t)b * Dh * SKn;
    const __nv_bfloat16* Vl = g_Vl + (size_t)b * Dh * SKn;
    float* strip = g_S + ((size_t)(b * NQT + qt)) * ((size_t)128 * SKn);
    __nv_bfloat16* Ph = g_Ph + ((size_t)b * SQn + qt * 128) * SKn;
    __nv_bfloat16* Pl = g_Pl + ((size_t)b * SQn + qt * 128) * SKn;

    if (tid < 128) rowmax[tid] = -1e30f;
    __syncthreads();

    // ldmatrix per-lane byte offsets within a tile
    const uint32_t aoff = (uint32_t)((wq * 16 + (lane & 7) + ((lane >> 3) & 1) * 8) * PITCHB
                                     + (lane >> 4) * 16);
    const uint32_t boff = (uint32_t)((nh * 64 + (lane & 7) + (lane >> 4) * 8) * PITCHB
                                     + ((lane >> 3) & 1) * 16);

    float acc[8][4];

    // ================= PHASE 1: S = Q K^T (bf16x3) =================
    for (int kt = 0; kt < NKT; kt++) {
        #pragma unroll
        for (int f = 0; f < 8; f++)
            #pragma unroll
            for (int j = 0; j < 4; j++) acc[f][j] = 0.0f;

        for (int dc = 0; dc < NDC; dc++) {
            #pragma unroll
            for (int j = 0; j < 4; j++) {
                int idx = tid + j * THREADS;         // 0..2047
                int r = idx >> 4, c = idx & 15;
                uint32_t d = (uint32_t)(r * PITCHB + c * 16);
                size_t qo = (size_t)r * Dh + dc * 128 + c * 8;
                size_t ko = (size_t)(kt * 128 + r) * Dh + dc * 128 + c * 8;
                cpasync16(sAH + d, Qh + qo);
                cpasync16(sAL + d, Ql + qo);
                cpasync16(sBH + d, Kh + ko);
                cpasync16(sBL + d, Kl + ko);
            }
            CP_COMMIT(); CP_WAIT0();
            __syncthreads();
            for (int ks = 0; ks < 8; ks++) {
                uint32_t ah[4], al[4];
                ldsm4(ah, sAH + aoff + ks * 32);
                ldsm4(al, sAL + aoff + ks * 32);
                #pragma unroll
                for (int f = 0; f < 4; f++) {
                    uint32_t bh[4], bl[4];
                    uint32_t bo = boff + (uint32_t)(f * (16 * PITCHB) + ks * 32);
                    ldsm4(bh, sBH + bo);
                    ldsm4(bl, sBL + bo);
                    mma16816(acc[2 * f],     ah, bh);
                    mma16816(acc[2 * f],     ah, bl);
                    mma16816(acc[2 * f],     al, bh);
                    mma16816(acc[2 * f + 1], ah, bh + 2);
                    mma16816(acc[2 * f + 1], ah, bl + 2);
                    mma16816(acc[2 * f + 1], al, bh + 2);
                }
            }
            __syncthreads();
        }
        // fragments -> stage
        {
            int row = wq * 16 + (lane >> 2);
            int cb = nh * 64 + (lane & 3) * 2;
            #pragma unroll
            for (int f = 0; f < 8; f++) {
                *(float2*)&stage[row * 136 + cb + f * 8] = make_float2(acc[f][0], acc[f][1]);
                *(float2*)&stage[(row + 8) * 136 + cb + f * 8] = make_float2(acc[f][2], acc[f][3]);
            }
        }
        __syncthreads();
        // stage -> strip (coalesced) + rowmax (one warp covers one row per iter)
        #pragma unroll
        for (int j = 0; j < 8; j++) {
            int i = tid + j * THREADS;
            int r = i >> 5, c4 = (i & 31) << 2;
            float4 v = *(const float4*)&stage[r * 136 + c4];
            *(float4*)(strip + (size_t)kt * 16384 + r * 128 + c4) = v;
            float m = fmaxf(fmaxf(v.x, v.y), fmaxf(v.z, v.w));
            m = fmaxf(m, __shfl_xor_sync(0xffffffffu, m, 16));
            m = fmaxf(m, __shfl_xor_sync(0xffffffffu, m, 8));
            m = fmaxf(m, __shfl_xor_sync(0xffffffffu, m, 4));
            m = fmaxf(m, __shfl_xor_sync(0xffffffffu, m, 2));
            m = fmaxf(m, __shfl_xor_sync(0xffffffffu, m, 1));
            if (lane == 0) rowmax[r] = fmaxf(rowmax[r], m);
        }
        __syncthreads();
    }

    // ================= PHASE 2: softmax + split P to Ph/Pl =================
    for (int i = 0; i < 8; i++) {
        int r = wid * 8 + i;
        float m = rowmax[r], s = 0.0f;
        for (int kt = 0; kt < NKT; kt++) {
            float4 vv = *(const float4*)(strip + (size_t)kt * 16384 + r * 128 + lane * 4);
            float p0 = __expf(vv.x - m), p1 = __expf(vv.y - m);
            float p2 = __expf(vv.z - m), p3 = __expf(vv.w - m);
            s += (p0 + p1) + (p2 + p3);
            __nv_bfloat16 h0 = __float2bfloat16(p0), h1 = __float2bfloat16(p1);
            __nv_bfloat16 h2 = __float2bfloat16(p2), h3 = __float2bfloat16(p3);
            uint2 hw;
            hw.x = (uint32_t)us(h0) | ((uint32_t)us(h1) << 16);
            hw.y = (uint32_t)us(h2) | ((uint32_t)us(h3) << 16);
            *(uint2*)(Ph + (size_t)r * SKn + kt * 128 + lane * 4) = hw;
            __nv_bfloat16 l0 = __float2bfloat16(p0 - __bfloat162float(h0));
            __nv_bfloat16 l1 = __float2bfloat16(p1 - __bfloat162float(h1));
            __nv_bfloat16 l2 = __float2bfloat16(p2 - __bfloat162float(h2));
            __nv_bfloat16 l3 = __float2bfloat16(p3 - __bfloat162float(h3));
            uint2 lw;
            lw.x = (uint32_t)us(l0) | ((uint32_t)us(l1) << 16);
            lw.y = (uint32_t)us(l2) | ((uint32_t)us(l3) << 16);
            *(uint2*)(Pl + (size_t)r * SKn + kt * 128 + lane * 4) = lw;
        }
        #pragma unroll
        for (int off = 16; off; off >>= 1) s += __shfl_xor_sync(0xffffffffu, s, off);
        if (lane == 0) rowsum[r] = s;
    }
    __syncthreads();

    // ================= PHASE 3: O = P V (bf16x3) =================
    for (int dc = 0; dc < NDC; dc++) {
        #pragma unroll
        for (int f = 0; f < 8; f++)
            #pragma unroll
            for (int j = 0; j < 4; j++) acc[f][j] = 0.0f;

        for (int kt = 0; kt < NKT; kt++) {
            #pragma unroll
            for (int j = 0; j < 4; j++) {
                int idx = tid + j * THREADS;
                int r = idx >> 4, c = idx & 15;
                uint32_t d = (uint32_t)(r * PITCHB + c * 16);
                size_t po = (size_t)r * SKn + kt * 128 + c * 8;
                size_t vo = (size_t)(dc * 128 + r) * SKn + kt * 128 + c * 8;
                cpasync16(sAH + d, Ph + po);
                cpasync16(sAL + d, Pl + po);
                cpasync16(sBH + d, Vh + vo);
                cpasync16(sBL + d, Vl + vo);
            }
            CP_COMMIT(); CP_WAIT0();
            __syncthreads();
            for (int ks = 0; ks < 8; ks++) {
                uint32_t ah[4], al[4];
                ldsm4(ah, sAH + aoff + ks * 32);
                ldsm4(al, sAL + aoff + ks * 32);
                #pragma unroll
                for (int f = 0; f < 4; f++) {
                    uint32_t bh[4], bl[4];
                    uint32_t bo = boff + (uint32_t)(f * (16 * PITCHB) + ks * 32);
                    ldsm4(bh, sBH + bo);
                    ldsm4(bl, sBL + bo);
                    mma16816(acc[2 * f],     ah, bh);
                    mma16816(acc[2 * f],     ah, bl);
                    mma16816(acc[2 * f],     al, bh);
                    mma16816(acc[2 * f + 1], ah, bh + 2);
                    mma16816(acc[2 * f + 1], ah, bl + 2);
                    mma16816(acc[2 * f + 1], al, bh + 2);
                }
            }
            __syncthreads();
        }
        // epilogue for this d-chunk
        {
            int row = wq * 16 + (lane >> 2);
            float inv0 = 1.0f / rowsum[row];
            float inv1 = 1.0f / rowsum[row + 8];
            float* o0 = out + ((size_t)b * SQn + qt * 128 + row) * Dh + dc * 128 + nh * 64 + (lane & 3) * 2;
            float* o1 = o0 + 8 * Dh;
            #pragma unroll
            for (int f = 0; f < 8; f++) {
                *(float2*)(o0 + f * 8) = make_float2(acc[f][0] * inv0, acc[f][1] * inv0);
                *(float2*)(o1 + f * 8) = make_float2(acc[f][2] * inv1, acc[f][3] * inv1);
            }
        }
    }
}

extern "C" void kernel_launch(void* const* d_in, const int* in_sizes, int n_in,
                              void* d_out, int out_size) {
    (void)in_sizes; (void)n_in; (void)out_size;
    const float* q = (const float*)d_in[0];
    const float* k = (const float*)d_in[1];
    const float* v = (const float*)d_in[2];
    float* out = (float*)d_out;

    cudaFuncSetAttribute(attn_main, cudaFuncAttributeMaxDynamicSharedMemorySize, SMEM_BYTES);

    prep_qk<<<4096, 256>>>(q, k);
    dim3 vgrid(SKn / 32, Dh / 32, Bn);
    prep_v<<<vgrid, 256>>>(v);
    dim3 grid(NQT, Bn);
    attn_main<<<grid, THREADS, SMEM_BYTES>>>(out);
}

// round 5
// speedup vs baseline: 1.6216x; 1.0647x over previous
#include <cuda_runtime.h>
#include <cuda_bf16.h>
#include <cstdint>

#define Bn 8
#define SQn 2048
#define SKn 2048
#define Dh 512
#define NKT 16
#define NQT 16
#define THREADS 512
#define PITCHB 144                 // bytes per smem tile row (64 bf16 + 16B pad)
#define TB2 (128 * PITCHB)         // 18432 bytes per tile
#define BUFB (4 * TB2)             // 73728 per stage-buffer (AH, AL, BH, BL)
#define STAGE_OFF 1024
#define STAGE_BYTES (128 * 136 * 4)
#define TILES_OFF (STAGE_OFF + STAGE_BYTES)
#define SMEM_BYTES (TILES_OFF + 2 * BUFB)

__device__ __nv_bfloat16 g_Qh[Bn * SQn * Dh], g_Ql[Bn * SQn * Dh];
__device__ __nv_bfloat16 g_Kh[Bn * SKn * Dh], g_Kl[Bn * SKn * Dh];
__device__ __nv_bfloat16 g_Vh[Bn * SKn * Dh], g_Vl[Bn * SKn * Dh];   // [b][d][sk]
__device__ float g_S[(size_t)Bn * SQn * SKn];
__device__ __nv_bfloat16 g_Ph[(size_t)Bn * SQn * SKn], g_Pl[(size_t)Bn * SQn * SKn];

// ---------------- helpers ----------------
__device__ __forceinline__ uint32_t smem_to_u32(const void* p) {
    uint32_t a;
    asm("{ .reg .u64 t; cvta.to.shared.u64 t, %1; cvt.u32.u64 %0, t; }" : "=r"(a) : "l"(p));
    return a;
}
__device__ __forceinline__ void ldsm4(uint32_t* r, uint32_t addr) {
    asm volatile("ldmatrix.sync.aligned.m8n8.x4.shared.b16 {%0,%1,%2,%3}, [%4];"
        : "=r"(r[0]), "=r"(r[1]), "=r"(r[2]), "=r"(r[3]) : "r"(addr));
}
__device__ __forceinline__ void mma16816(float* c, const uint32_t* a, const uint32_t* b) {
    asm volatile("mma.sync.aligned.m16n8k16.row.col.f32.bf16.bf16.f32 "
        "{%0,%1,%2,%3}, {%4,%5,%6,%7}, {%8,%9}, {%0,%1,%2,%3};"
        : "+f"(c[0]), "+f"(c[1]), "+f"(c[2]), "+f"(c[3])
        : "r"(a[0]), "r"(a[1]), "r"(a[2]), "r"(a[3]), "r"(b[0]), "r"(b[1]));
}
__device__ __forceinline__ void cpasync16(uint32_t dst, const void* src) {
    asm volatile("cp.async.cg.shared.global [%0], [%1], 16;" :: "r"(dst), "l"(src));
}
#define CP_COMMIT() asm volatile("cp.async.commit_group;" ::: "memory")
#define CP_WAIT0()  asm volatile("cp.async.wait_group 0;" ::: "memory")
__device__ __forceinline__ unsigned short us(__nv_bfloat16 h) { return __bfloat16_as_ushort(h); }

// ---------------- prep ----------------
__global__ void prep_qk(const float* __restrict__ q, const float* __restrict__ k) {
    const int n = Bn * SQn * Dh;
    for (int i = blockIdx.x * blockDim.x + threadIdx.x; i < n; i += gridDim.x * blockDim.x) {
        float x = q[i];
        __nv_bfloat16 h = __float2bfloat16(x);
        g_Qh[i] = h;
        g_Ql[i] = __float2bfloat16(x - __bfloat162float(h));
        float y = k[i];
        __nv_bfloat16 g = __float2bfloat16(y);
        g_Kh[i] = g;
        g_Kl[i] = __float2bfloat16(y - __bfloat162float(g));
    }
}
__global__ void prep_v(const float* __restrict__ v) {
    __shared__ float t[32][33];
    const int b = blockIdx.z;
    const int sk0 = blockIdx.x * 32, d0 = blockIdx.y * 32;
    const int tx = threadIdx.x & 31, ty = threadIdx.x >> 5;
    #pragma unroll
    for (int rr = 0; rr < 32; rr += 8)
        t[ty + rr][tx] = v[(((size_t)b * SKn + sk0 + ty + rr) << 9) + d0 + tx];
    __syncthreads();
    #pragma unroll
    for (int rr = 0; rr < 32; rr += 8) {
        int d = d0 + ty + rr;
        float x = t[tx][ty + rr];
        __nv_bfloat16 h = __float2bfloat16(x);
        size_t o = ((size_t)b * Dh + d) * SKn + sk0 + tx;
        g_Vh[o] = h;
        g_Vl[o] = __float2bfloat16(x - __bfloat162float(h));
    }
}

__global__ void __launch_bounds__(THREADS, 1)
attn_main(float* __restrict__ out) {
    extern __shared__ char smem[];
    float* rowmax = (float*)smem;
    float* rowsum = (float*)(smem + 512);
    float* stage = (float*)(smem + STAGE_OFF);     // 128 x 136 fp32

    const uint32_t sTiles = smem_to_u32(smem) + TILES_OFF;

    const int tid = threadIdx.x, wid = tid >> 5, lane = tid & 31;
    const int wq = wid >> 1, nh = wid & 1;
    const int qt = blockIdx.x, b = blockIdx.y;

    const __nv_bfloat16* Qh = g_Qh + ((size_t)b * SQn + qt * 128) * Dh;
    const __nv_bfloat16* Ql = g_Ql + ((size_t)b * SQn + qt * 128) * Dh;
    const __nv_bfloat16* Kh = g_Kh + (size_t)b * SKn * Dh;
    const __nv_bfloat16* Kl = g_Kl + (size_t)b * SKn * Dh;
    const __nv_bfloat16* Vh = g_Vh + (size_t)b * Dh * SKn;
    const __nv_bfloat16* Vl = g_Vl + (size_t)b * Dh * SKn;
    float* strip = g_S + ((size_t)(b * NQT + qt)) * ((size_t)128 * SKn);
    __nv_bfloat16* Ph = g_Ph + ((size_t)b * SQn + qt * 128) * SKn;
    __nv_bfloat16* Pl = g_Pl + ((size_t)b * SQn + qt * 128) * SKn;

    if (tid < 128) rowmax[tid] = -1e30f;

    // per-lane ldmatrix byte offsets within a tile (pitch 144B, 64 k-cols)
    const uint32_t aoff = (uint32_t)((wq * 16 + (lane & 7) + ((lane >> 3) & 1) * 8) * PITCHB
                                     + (lane >> 4) * 16);
    const uint32_t boff = (uint32_t)((nh * 64 + (lane & 7) + (lane >> 4) * 8) * PITCHB
                                     + ((lane >> 3) & 1) * 16);
    // per-thread fill coords: 1024 16B-chunks per tile, 2 per thread
    const int fr0 = tid >> 2, fc0 = (tid & 3) << 1;   // rows 0..127, chunk pairs

    float acc[8][4];

    // ================= PHASE 1: S = Q K^T (bf16x3) =================
    // step = kt*8 + dc  (k-chunks of 64 over Dh)
    {
        // prologue: load step 0 into buf 0
        {
            uint32_t base = sTiles;
            #pragma unroll
            for (int j = 0; j < 2; j++) {
                int r = fr0, c = fc0 + j;
                uint32_t d = base + (uint32_t)(r * PITCHB + c * 16);
                size_t qo = (size_t)r * Dh + c * 8;
                size_t ko = (size_t)r * Dh + c * 8;
                cpasync16(d, Qh + qo);
                cpasync16(d + TB2, Ql + qo);
                cpasync16(d + 2 * TB2, Kh + ko);
                cpasync16(d + 3 * TB2, Kl + ko);
            }
            CP_COMMIT();
        }
        for (int step = 0; step < 128; step++) {
            const int dc = step & 7;
            if (dc == 0) {
                #pragma unroll
                for (int f = 0; f < 8; f++)
                    #pragma unroll
                    for (int j = 0; j < 4; j++) acc[f][j] = 0.0f;
            }
            CP_WAIT0();
            __syncthreads();
            if (step + 1 < 128) {
                int kt1 = (step + 1) >> 3, dc1 = (step + 1) & 7;
                uint32_t base = sTiles + ((step + 1) & 1) * BUFB;
                #pragma unroll
                for (int j = 0; j < 2; j++) {
                    int r = fr0, c = fc0 + j;
                    uint32_t d = base + (uint32_t)(r * PITCHB + c * 16);
                    size_t qo = (size_t)r * Dh + dc1 * 64 + c * 8;
                    size_t ko = (size_t)(kt1 * 128 + r) * Dh + dc1 * 64 + c * 8;
                    cpasync16(d, Qh + qo);
                    cpasync16(d + TB2, Ql + qo);
                    cpasync16(d + 2 * TB2, Kh + ko);
                    cpasync16(d + 3 * TB2, Kl + ko);
                }
                CP_COMMIT();
            }
            const uint32_t sAH = sTiles + (step & 1) * BUFB;
            const uint32_t sAL = sAH + TB2, sBH = sAH + 2 * TB2, sBL = sAH + 3 * TB2;
            #pragma unroll
            for (int ks = 0; ks < 4; ks++) {
                uint32_t ah[4], al[4];
                ldsm4(ah, sAH + aoff + ks * 32);
                ldsm4(al, sAL + aoff + ks * 32);
                #pragma unroll
                for (int f = 0; f < 4; f++) {
                    uint32_t bh[4], bl[4];
                    uint32_t bo = boff + (uint32_t)(f * (16 * PITCHB) + ks * 32);
                    ldsm4(bh, sBH + bo);
                    ldsm4(bl, sBL + bo);
                    mma16816(acc[2 * f],     ah, bh);
                    mma16816(acc[2 * f],     ah, bl);
                    mma16816(acc[2 * f],     al, bh);
                    mma16816(acc[2 * f + 1], ah, bh + 2);
                    mma16816(acc[2 * f + 1], ah, bl + 2);
                    mma16816(acc[2 * f + 1], al, bh + 2);
                }
            }
            if (dc == 7) {   // spill this kt's S tile
                const int kt = step >> 3;
                int row = wq * 16 + (lane >> 2);
                int cb = nh * 64 + (lane & 3) * 2;
                #pragma unroll
                for (int f = 0; f < 8; f++) {
                    *(float2*)&stage[row * 136 + cb + f * 8] = make_float2(acc[f][0], acc[f][1]);
                    *(float2*)&stage[(row + 8) * 136 + cb + f * 8] = make_float2(acc[f][2], acc[f][3]);
                }
                __syncthreads();
                #pragma unroll
                for (int j = 0; j < 8; j++) {
                    int i = tid + j * THREADS;
                    int r = i >> 5, c4 = (i & 31) << 2;
                    float4 v = *(const float4*)&stage[r * 136 + c4];
                    *(float4*)(strip + (size_t)kt * 16384 + r * 128 + c4) = v;
                    float m = fmaxf(fmaxf(v.x, v.y), fmaxf(v.z, v.w));
                    m = fmaxf(m, __shfl_xor_sync(0xffffffffu, m, 16));
                    m = fmaxf(m, __shfl_xor_sync(0xffffffffu, m, 8));
                    m = fmaxf(m, __shfl_xor_sync(0xffffffffu, m, 4));
                    m = fmaxf(m, __shfl_xor_sync(0xffffffffu, m, 2));
                    m = fmaxf(m, __shfl_xor_sync(0xffffffffu, m, 1));
                    if (lane == 0) rowmax[r] = fmaxf(rowmax[r], m);
                }
            }
        }
    }
    __syncthreads();

    // ================= PHASE 2: softmax + split P to Ph/Pl =================
    for (int i = 0; i < 8; i++) {
        int r = wid * 8 + i;
        float m = rowmax[r], s = 0.0f;
        for (int kt = 0; kt < NKT; kt++) {
            float4 vv = *(const float4*)(strip + (size_t)kt * 16384 + r * 128 + lane * 4);
            float p0 = __expf(vv.x - m), p1 = __expf(vv.y - m);
            float p2 = __expf(vv.z - m), p3 = __expf(vv.w - m);
            s += (p0 + p1) + (p2 + p3);
            __nv_bfloat16 h0 = __float2bfloat16(p0), h1 = __float2bfloat16(p1);
            __nv_bfloat16 h2 = __float2bfloat16(p2), h3 = __float2bfloat16(p3);
            uint2 hw;
            hw.x = (uint32_t)us(h0) | ((uint32_t)us(h1) << 16);
            hw.y = (uint32_t)us(h2) | ((uint32_t)us(h3) << 16);
            *(uint2*)(Ph + (size_t)r * SKn + kt * 128 + lane * 4) = hw;
            __nv_bfloat16 l0 = __float2bfloat16(p0 - __bfloat162float(h0));
            __nv_bfloat16 l1 = __float2bfloat16(p1 - __bfloat162float(h1));
            __nv_bfloat16 l2 = __float2bfloat16(p2 - __bfloat162float(h2));
            __nv_bfloat16 l3 = __float2bfloat16(p3 - __bfloat162float(h3));
            uint2 lw;
            lw.x = (uint32_t)us(l0) | ((uint32_t)us(l1) << 16);
            lw.y = (uint32_t)us(l2) | ((uint32_t)us(l3) << 16);
            *(uint2*)(Pl + (size_t)r * SKn + kt * 128 + lane * 4) = lw;
        }
        #pragma unroll
        for (int off = 16; off; off >>= 1) s += __shfl_xor_sync(0xffffffffu, s, off);
        if (lane == 0) rowsum[r] = s;
    }
    __syncthreads();

    // ================= PHASE 3: O = P V (bf16x3) =================
    // step = dc*32 + t, t = 64-col chunk over SK
    {
        {
            uint32_t base = sTiles;
            #pragma unroll
            for (int j = 0; j < 2; j++) {
                int r = fr0, c = fc0 + j;
                uint32_t d = base + (uint32_t)(r * PITCHB + c * 16);
                size_t po = (size_t)r * SKn + c * 8;
                size_t vo = (size_t)r * SKn + c * 8;
                cpasync16(d, Ph + po);
                cpasync16(d + TB2, Pl + po);
                cpasync16(d + 2 * TB2, Vh + vo);
                cpasync16(d + 3 * TB2, Vl + vo);
            }
            CP_COMMIT();
        }
        for (int step = 0; step < 128; step++) {
            const int dc = step >> 5, t = step & 31;
            if (t == 0) {
                #pragma unroll
                for (int f = 0; f < 8; f++)
                    #pragma unroll
                    for (int j = 0; j < 4; j++) acc[f][j] = 0.0f;
            }
            CP_WAIT0();
            __syncthreads();
            if (step + 1 < 128) {
                int dc1 = (step + 1) >> 5, t1 = (step + 1) & 31;
                uint32_t base = sTiles + ((step + 1) & 1) * BUFB;
                #pragma unroll
                for (int j = 0; j < 2; j++) {
                    int r = fr0, c = fc0 + j;
                    uint32_t d = base + (uint32_t)(r * PITCHB + c * 16);
                    size_t po = (size_t)r * SKn + t1 * 64 + c * 8;
                    size_t vo = (size_t)(dc1 * 128 + r) * SKn + t1 * 64 + c * 8;
                    cpasync16(d, Ph + po);
                    cpasync16(d + TB2, Pl + po);
                    cpasync16(d + 2 * TB2, Vh + vo);
                    cpasync16(d + 3 * TB2, Vl + vo);
                }
                CP_COMMIT();
            }
            const uint32_t sAH = sTiles + (step & 1) * BUFB;
            const uint32_t sAL = sAH + TB2, sBH = sAH + 2 * TB2, sBL = sAH + 3 * TB2;
            #pragma unroll
            for (int ks = 0; ks < 4; ks++) {
                uint32_t ah[4], al[4];
                ldsm4(ah, sAH + aoff + ks * 32);
                ldsm4(al, sAL + aoff + ks * 32);
                #pragma unroll
                for (int f = 0; f < 4; f++) {
                    uint32_t bh[4], bl[4];
                    uint32_t bo = boff + (uint32_t)(f * (16 * PITCHB) + ks * 32);
                    ldsm4(bh, sBH + bo);
                    ldsm4(bl, sBL + bo);
                    mma16816(acc[2 * f],     ah, bh);
                    mma16816(acc[2 * f],     ah, bl);
                    mma16816(acc[2 * f],     al, bh);
                    mma16816(acc[2 * f + 1], ah, bh + 2);
                    mma16816(acc[2 * f + 1], ah, bl + 2);
                    mma16816(acc[2 * f + 1], al, bh + 2);
                }
            }
            if (t == 31) {   // epilogue for this d-chunk
                int row = wq * 16 + (lane >> 2);
                float inv0 = 1.0f / rowsum[row];
                float inv1 = 1.0f / rowsum[row + 8];
                float* o0 = out + ((size_t)b * SQn + qt * 128 + row) * Dh + dc * 128 + nh * 64 + (lane & 3) * 2;
                float* o1 = o0 + 8 * Dh;
                #pragma unroll
                for (int f = 0; f < 8; f++) {
                    *(float2*)(o0 + f * 8) = make_float2(acc[f][0] * inv0, acc[f][1] * inv0);
                    *(float2*)(o1 + f * 8) = make_float2(acc[f][2] * inv1, acc[f][3] * inv1);
                }
            }
        }
    }
}

extern "C" void kernel_launch(void* const* d_in, const int* in_sizes, int n_in,
                              void* d_out, int out_size) {
    (void)in_sizes; (void)n_in; (void)out_size;
    const float* q = (const float*)d_in[0];
    const float* k = (const float*)d_in[1];
    const float* v = (const float*)d_in[2];
    float* out = (float*)d_out;

    cudaFuncSetAttribute(attn_main, cudaFuncAttributeMaxDynamicSharedMemorySize, SMEM_BYTES);

    prep_qk<<<4096, 256>>>(q, k);
    dim3 vgrid(SKn / 32, Dh / 32, Bn);
    prep_v<<<vgrid, 256>>>(v);
    dim3 grid(NQT, Bn);
    attn_main<<<grid, THREADS, SMEM_BYTES>>>(out);
}

// round 6
// speedup vs baseline: 1.6938x; 1.0445x over previous
#include <cuda_runtime.h>
#include <cuda_bf16.h>
#include <cstdint>

#define Bn 8
#define SQn 2048
#define SKn 2048
#define Dh 512
#define NKT 16
#define NQT 16
#define THREADS 512
#define PITCHB 144                 // bytes per smem tile row (64 bf16 + 16B pad)
#define TB2 (128 * PITCHB)         // 18432 bytes per tile
#define BUFB (4 * TB2)             // 73728 per buffer (AH, AL, BH, BL)
#define NSTAGE 3
#define TILES_OFF 2048
#define SMEM_BYTES (TILES_OFF + NSTAGE * BUFB)

__device__ __nv_bfloat16 g_Qh[Bn * SQn * Dh], g_Ql[Bn * SQn * Dh];
__device__ __nv_bfloat16 g_Kh[Bn * SKn * Dh], g_Kl[Bn * SKn * Dh];
__device__ __nv_bfloat16 g_Vh[Bn * SKn * Dh], g_Vl[Bn * SKn * Dh];   // [b][d][sk]
__device__ float g_S[(size_t)Bn * SQn * SKn];
__device__ __nv_bfloat16 g_Ph[(size_t)Bn * SQn * SKn], g_Pl[(size_t)Bn * SQn * SKn];

// ---------------- helpers ----------------
__device__ __forceinline__ uint32_t smem_to_u32(const void* p) {
    uint32_t a;
    asm("{ .reg .u64 t; cvta.to.shared.u64 t, %1; cvt.u32.u64 %0, t; }" : "=r"(a) : "l"(p));
    return a;
}
__device__ __forceinline__ void ldsm4(uint32_t* r, uint32_t addr) {
    asm volatile("ldmatrix.sync.aligned.m8n8.x4.shared.b16 {%0,%1,%2,%3}, [%4];"
        : "=r"(r[0]), "=r"(r[1]), "=r"(r[2]), "=r"(r[3]) : "r"(addr));
}
__device__ __forceinline__ void mma16816(float* c, const uint32_t* a, const uint32_t* b) {
    asm volatile("mma.sync.aligned.m16n8k16.row.col.f32.bf16.bf16.f32 "
        "{%0,%1,%2,%3}, {%4,%5,%6,%7}, {%8,%9}, {%0,%1,%2,%3};"
        : "+f"(c[0]), "+f"(c[1]), "+f"(c[2]), "+f"(c[3])
        : "r"(a[0]), "r"(a[1]), "r"(a[2]), "r"(a[3]), "r"(b[0]), "r"(b[1]));
}
__device__ __forceinline__ void cpasync16(uint32_t dst, const void* src) {
    asm volatile("cp.async.cg.shared.global [%0], [%1], 16;" :: "r"(dst), "l"(src));
}
#define CP_COMMIT() asm volatile("cp.async.commit_group;" ::: "memory")
#define CP_WAIT1()  asm volatile("cp.async.wait_group 1;" ::: "memory")
__device__ __forceinline__ unsigned short us(__nv_bfloat16 h) { return __bfloat16_as_ushort(h); }

// ---------------- prep ----------------
__global__ void prep_qk(const float* __restrict__ q, const float* __restrict__ k) {
    const int n = Bn * SQn * Dh;
    for (int i = blockIdx.x * blockDim.x + threadIdx.x; i < n; i += gridDim.x * blockDim.x) {
        float x = q[i];
        __nv_bfloat16 h = __float2bfloat16(x);
        g_Qh[i] = h;
        g_Ql[i] = __float2bfloat16(x - __bfloat162float(h));
        float y = k[i];
        __nv_bfloat16 g = __float2bfloat16(y);
        g_Kh[i] = g;
        g_Kl[i] = __float2bfloat16(y - __bfloat162float(g));
    }
}
__global__ void prep_v(const float* __restrict__ v) {
    __shared__ float t[32][33];
    const int b = blockIdx.z;
    const int sk0 = blockIdx.x * 32, d0 = blockIdx.y * 32;
    const int tx = threadIdx.x & 31, ty = threadIdx.x >> 5;
    #pragma unroll
    for (int rr = 0; rr < 32; rr += 8)
        t[ty + rr][tx] = v[(((size_t)b * SKn + sk0 + ty + rr) << 9) + d0 + tx];
    __syncthreads();
    #pragma unroll
    for (int rr = 0; rr < 32; rr += 8) {
        int d = d0 + ty + rr;
        float x = t[tx][ty + rr];
        __nv_bfloat16 h = __float2bfloat16(x);
        size_t o = ((size_t)b * Dh + d) * SKn + sk0 + tx;
        g_Vh[o] = h;
        g_Vl[o] = __float2bfloat16(x - __bfloat162float(h));
    }
}

__global__ void __launch_bounds__(THREADS, 1)
attn_main(float* __restrict__ out) {
    extern __shared__ char smem[];
    float* rowmax2 = (float*)smem;              // [2][128]
    float* rowsum = (float*)(smem + 1024);      // [128]
    const uint32_t sTiles = smem_to_u32(smem) + TILES_OFF;

    const int tid = threadIdx.x, wid = tid >> 5, lane = tid & 31;
    const int wq = wid >> 1, nh = wid & 1;
    const int qt = blockIdx.x, b = blockIdx.y;

    const __nv_bfloat16* Qh = g_Qh + ((size_t)b * SQn + qt * 128) * Dh;
    const __nv_bfloat16* Ql = g_Ql + ((size_t)b * SQn + qt * 128) * Dh;
    const __nv_bfloat16* Kh = g_Kh + (size_t)b * SKn * Dh;
    const __nv_bfloat16* Kl = g_Kl + (size_t)b * SKn * Dh;
    const __nv_bfloat16* Vh = g_Vh + (size_t)b * Dh * SKn;
    const __nv_bfloat16* Vl = g_Vl + (size_t)b * Dh * SKn;
    float* strip = g_S + ((size_t)(b * NQT + qt)) * ((size_t)128 * SKn);
    __nv_bfloat16* Ph = g_Ph + ((size_t)b * SQn + qt * 128) * SKn;
    __nv_bfloat16* Pl = g_Pl + ((size_t)b * SQn + qt * 128) * SKn;

    if (tid < 256) rowmax2[tid] = -1e30f;

    // per-lane ldmatrix byte offsets within a tile (pitch 144B, 64 k-cols)
    const uint32_t aoff = (uint32_t)((wq * 16 + (lane & 7) + ((lane >> 3) & 1) * 8) * PITCHB
                                     + (lane >> 4) * 16);
    const uint32_t boff = (uint32_t)((nh * 64 + (lane & 7) + (lane >> 4) * 8) * PITCHB
                                     + ((lane >> 3) & 1) * 16);
    const int fr0 = tid >> 2, fc0 = (tid & 3) << 1;   // fill: row, chunk pair

    float acc[8][4];

    // ================= PHASE 1: S = Q K^T (bf16x3) =================
    // step = kt*8 + dc (k-chunks of 64 over Dh); 3-stage pipeline
    {
        #pragma unroll
        for (int s = 0; s < 2; s++) {          // prologue: steps 0,1
            uint32_t base = sTiles + s * BUFB;
            int kt1 = s >> 3, dc1 = s & 7;
            #pragma unroll
            for (int j = 0; j < 2; j++) {
                int r = fr0, c = fc0 + j;
                uint32_t d = base + (uint32_t)(r * PITCHB + c * 16);
                size_t qo = (size_t)r * Dh + dc1 * 64 + c * 8;
                size_t ko = (size_t)(kt1 * 128 + r) * Dh + dc1 * 64 + c * 8;
                cpasync16(d, Qh + qo);
                cpasync16(d + TB2, Ql + qo);
                cpasync16(d + 2 * TB2, Kh + ko);
                cpasync16(d + 3 * TB2, Kl + ko);
            }
            CP_COMMIT();
        }
        for (int step = 0; step < 128; step++) {
            const int dc = step & 7;
            if (dc == 0) {
                #pragma unroll
                for (int f = 0; f < 8; f++)
                    #pragma unroll
                    for (int j = 0; j < 4; j++) acc[f][j] = 0.0f;
            }
            CP_WAIT1();
            __syncthreads();
            if (step + 2 < 128) {
                int s2 = step + 2;
                int kt1 = s2 >> 3, dc1 = s2 & 7;
                uint32_t base = sTiles + (s2 % NSTAGE) * BUFB;
                #pragma unroll
                for (int j = 0; j < 2; j++) {
                    int r = fr0, c = fc0 + j;
                    uint32_t d = base + (uint32_t)(r * PITCHB + c * 16);
                    size_t qo = (size_t)r * Dh + dc1 * 64 + c * 8;
                    size_t ko = (size_t)(kt1 * 128 + r) * Dh + dc1 * 64 + c * 8;
                    cpasync16(d, Qh + qo);
                    cpasync16(d + TB2, Ql + qo);
                    cpasync16(d + 2 * TB2, Kh + ko);
                    cpasync16(d + 3 * TB2, Kl + ko);
                }
            }
            CP_COMMIT();   // (possibly empty) keeps wait_group count aligned
            const uint32_t sAH = sTiles + (step % NSTAGE) * BUFB;
            const uint32_t sAL = sAH + TB2, sBH = sAH + 2 * TB2, sBL = sAH + 3 * TB2;
            #pragma unroll
            for (int ks = 0; ks < 4; ks++) {
                uint32_t ah[4], al[4];
                ldsm4(ah, sAH + aoff + ks * 32);
                ldsm4(al, sAL + aoff + ks * 32);
                #pragma unroll
                for (int f = 0; f < 4; f++) {
                    uint32_t bh[4], bl[4];
                    uint32_t bo = boff + (uint32_t)(f * (16 * PITCHB) + ks * 32);
                    ldsm4(bh, sBH + bo);
                    ldsm4(bl, sBL + bo);
                    mma16816(acc[2 * f],     ah, bh);
                    mma16816(acc[2 * f],     ah, bl);
                    mma16816(acc[2 * f],     al, bh);
                    mma16816(acc[2 * f + 1], ah, bh + 2);
                    mma16816(acc[2 * f + 1], ah, bl + 2);
                    mma16816(acc[2 * f + 1], al, bh + 2);
                }
            }
            if (dc == 7) {   // spill S tile: fragments -> strip directly
                const int kt = step >> 3;
                int row = wq * 16 + (lane >> 2);
                int cb = nh * 64 + (lane & 3) * 2;
                float* s0 = strip + (size_t)kt * 16384 + row * 128 + cb;
                float m0 = -1e30f, m1 = -1e30f;
                #pragma unroll
                for (int f = 0; f < 8; f++) {
                    m0 = fmaxf(m0, fmaxf(acc[f][0], acc[f][1]));
                    m1 = fmaxf(m1, fmaxf(acc[f][2], acc[f][3]));
                    *(float2*)(s0 + f * 8) = make_float2(acc[f][0], acc[f][1]);
                    *(float2*)(s0 + 8 * 128 + f * 8) = make_float2(acc[f][2], acc[f][3]);
                }
                m0 = fmaxf(m0, __shfl_xor_sync(0xffffffffu, m0, 1));
                m0 = fmaxf(m0, __shfl_xor_sync(0xffffffffu, m0, 2));
                m1 = fmaxf(m1, __shfl_xor_sync(0xffffffffu, m1, 1));
                m1 = fmaxf(m1, __shfl_xor_sync(0xffffffffu, m1, 2));
                if ((lane & 3) == 0) {
                    float* rm = rowmax2 + nh * 128;
                    rm[row] = fmaxf(rm[row], m0);
                    rm[row + 8] = fmaxf(rm[row + 8], m1);
                }
            }
        }
    }
    __syncthreads();

    // ================= PHASE 2: softmax + split P to Ph/Pl =================
    for (int i = 0; i < 8; i++) {
        int r = wid * 8 + i;
        float m = fmaxf(rowmax2[r], rowmax2[128 + r]);
        float s = 0.0f;
        for (int kt = 0; kt < NKT; kt++) {
            float4 vv = *(const float4*)(strip + (size_t)kt * 16384 + r * 128 + lane * 4);
            float p0 = __expf(vv.x - m), p1 = __expf(vv.y - m);
            float p2 = __expf(vv.z - m), p3 = __expf(vv.w - m);
            s += (p0 + p1) + (p2 + p3);
            __nv_bfloat16 h0 = __float2bfloat16(p0), h1 = __float2bfloat16(p1);
            __nv_bfloat16 h2 = __float2bfloat16(p2), h3 = __float2bfloat16(p3);
            uint2 hw;
            hw.x = (uint32_t)us(h0) | ((uint32_t)us(h1) << 16);
            hw.y = (uint32_t)us(h2) | ((uint32_t)us(h3) << 16);
            *(uint2*)(Ph + (size_t)r * SKn + kt * 128 + lane * 4) = hw;
            __nv_bfloat16 l0 = __float2bfloat16(p0 - __bfloat162float(h0));
            __nv_bfloat16 l1 = __float2bfloat16(p1 - __bfloat162float(h1));
            __nv_bfloat16 l2 = __float2bfloat16(p2 - __bfloat162float(h2));
            __nv_bfloat16 l3 = __float2bfloat16(p3 - __bfloat162float(h3));
            uint2 lw;
            lw.x = (uint32_t)us(l0) | ((uint32_t)us(l1) << 16);
            lw.y = (uint32_t)us(l2) | ((uint32_t)us(l3) << 16);
            *(uint2*)(Pl + (size_t)r * SKn + kt * 128 + lane * 4) = lw;
        }
        #pragma unroll
        for (int off = 16; off; off >>= 1) s += __shfl_xor_sync(0xffffffffu, s, off);
        if (lane == 0) rowsum[r] = s;
    }
    __syncthreads();

    // ================= PHASE 3: O = P V (bf16x3) =================
    // step = dc*32 + t (t = 64-col chunk over SK); 3-stage pipeline
    {
        #pragma unroll
        for (int s = 0; s < 2; s++) {
            uint32_t base = sTiles + s * BUFB;
            int dc1 = s >> 5, t1 = s & 31;
            #pragma unroll
            for (int j = 0; j < 2; j++) {
                int r = fr0, c = fc0 + j;
                uint32_t d = base + (uint32_t)(r * PITCHB + c * 16);
                size_t po = (size_t)r * SKn + t1 * 64 + c * 8;
                size_t vo = (size_t)(dc1 * 128 + r) * SKn + t1 * 64 + c * 8;
                cpasync16(d, Ph + po);
                cpasync16(d + TB2, Pl + po);
                cpasync16(d + 2 * TB2, Vh + vo);
                cpasync16(d + 3 * TB2, Vl + vo);
            }
            CP_COMMIT();
        }
        for (int step = 0; step < 128; step++) {
            const int dc = step >> 5, t = step & 31;
            if (t == 0) {
                #pragma unroll
                for (int f = 0; f < 8; f++)
                    #pragma unroll
                    for (int j = 0; j < 4; j++) acc[f][j] = 0.0f;
            }
            CP_WAIT1();
            __syncthreads();
            if (step + 2 < 128) {
                int s2 = step + 2;
                int dc1 = s2 >> 5, t1 = s2 & 31;
                uint32_t base = sTiles + (s2 % NSTAGE) * BUFB;
                #pragma unroll
                for (int j = 0; j < 2; j++) {
                    int r = fr0, c = fc0 + j;
                    uint32_t d = base + (uint32_t)(r * PITCHB + c * 16);
                    size_t po = (size_t)r * SKn + t1 * 64 + c * 8;
                    size_t vo = (size_t)(dc1 * 128 + r) * SKn + t1 * 64 + c * 8;
                    cpasync16(d, Ph + po);
                    cpasync16(d + TB2, Pl + po);
                    cpasync16(d + 2 * TB2, Vh + vo);
                    cpasync16(d + 3 * TB2, Vl + vo);
                }
            }
            CP_COMMIT();
            const uint32_t sAH = sTiles + (step % NSTAGE) * BUFB;
            const uint32_t sAL = sAH + TB2, sBH = sAH + 2 * TB2, sBL = sAH + 3 * TB2;
            #pragma unroll
            for (int ks = 0; ks < 4; ks++) {
                uint32_t ah[4], al[4];
                ldsm4(ah, sAH + aoff + ks * 32);
                ldsm4(al, sAL + aoff + ks * 32);
                #pragma unroll
                for (int f = 0; f < 4; f++) {
                    uint32_t bh[4], bl[4];
                    uint32_t bo = boff + (uint32_t)(f * (16 * PITCHB) + ks * 32);
                    ldsm4(bh, sBH + bo);
                    ldsm4(bl, sBL + bo);
                    mma16816(acc[2 * f],     ah, bh);
                    mma16816(acc[2 * f],     ah, bl);
                    mma16816(acc[2 * f],     al, bh);
                    mma16816(acc[2 * f + 1], ah, bh + 2);
                    mma16816(acc[2 * f + 1], ah, bl + 2);
                    mma16816(acc[2 * f + 1], al, bh + 2);
                }
            }
            if (t == 31) {   // epilogue for this d-chunk
                int row = wq * 16 + (lane >> 2);
                float inv0 = 1.0f / rowsum[row];
                float inv1 = 1.0f / rowsum[row + 8];
                float* o0 = out + ((size_t)b * SQn + qt * 128 + row) * Dh + dc * 128 + nh * 64 + (lane & 3) * 2;
                float* o1 = o0 + 8 * Dh;
                #pragma unroll
                for (int f = 0; f < 8; f++) {
                    *(float2*)(o0 + f * 8) = make_float2(acc[f][0] * inv0, acc[f][1] * inv0);
                    *(float2*)(o1 + f * 8) = make_float2(acc[f][2] * inv1, acc[f][3] * inv1);
                }
            }
        }
    }
}

extern "C" void kernel_launch(void* const* d_in, const int* in_sizes, int n_in,
                              void* d_out, int out_size) {
    (void)in_sizes; (void)n_in; (void)out_size;
    const float* q = (const float*)d_in[0];
    const float* k = (const float*)d_in[1];
    const float* v = (const float*)d_in[2];
    float* out = (float*)d_out;

    cudaFuncSetAttribute(attn_main, cudaFuncAttributeMaxDynamicSharedMemorySize, SMEM_BYTES);

    prep_qk<<<4096, 256>>>(q, k);
    dim3 vgrid(SKn / 32, Dh / 32, Bn);
    prep_v<<<vgrid, 256>>>(v);
    dim3 grid(NQT, Bn);
    attn_main<<<grid, THREADS, SMEM_BYTES>>>(out);
}